// round 2
// baseline (speedup 1.0000x reference)
#include <cuda_runtime.h>
#include <cuda_bf16.h>

// Problem constants (fixed by the reference setup)
constexpr int N_NODES = 50000;
constexpr int N_EDGES = 800000;
constexpr int NZ = N_NODES * 32;

// Scratch (device globals — no allocation allowed).
// NOTE: these are ONLY referenced from device code. Referencing a __device__
// symbol from host code (e.g. as a kernel argument) passes the host shadow
// address — on GB300 (ATS) that silently reads host memory. Round-1 bug.
__device__ __align__(16) float g_deg[N_NODES];
__device__ __align__(16) float g_dinv[N_NODES];
__device__ __align__(16) float g_ys32[N_NODES * 32];
__device__ __align__(16) float g_agg32[N_NODES * 32];
__device__ __align__(16) float g_ys64[N_NODES * 64];
__device__ __align__(16) float g_agg64[N_NODES * 64];
__device__ int g_is64;

// ---------------------------------------------------------------------------
// Helpers
// ---------------------------------------------------------------------------
__device__ __forceinline__ int edge_idx(const void* p, int pos) {
    if (g_is64) return (int)((const long long*)p)[pos];
    return ((const int*)p)[pos];
}

__device__ __forceinline__ void red_add4(float* addr, float4 v) {
    asm volatile("red.global.add.v4.f32 [%0], {%1,%2,%3,%4};"
                 :: "l"(addr), "f"(v.x), "f"(v.y), "f"(v.z), "f"(v.w)
                 : "memory");
}

// ---------------------------------------------------------------------------
// Detect int64 vs int32 edge_index (JAX may silently demote int64 -> int32).
// If the buffer really holds int32, interpreting pairs as int64 gives values
// >= 2^32 with overwhelming probability within 256 samples.
// ---------------------------------------------------------------------------
__global__ void detect_kernel(const void* ei) {
    if (threadIdx.x == 0 && blockIdx.x == 0) {
        const long long* p = (const long long*)ei;
        int ok = 1;
        for (int i = 0; i < 256; i++) {
            long long v = p[i];
            if (v < 0 || v >= N_NODES) { ok = 0; break; }
        }
        g_is64 = ok;
    }
}

// ---------------------------------------------------------------------------
// Init: deg = 1 (self-loop) and zero agg32 in one pass
// ---------------------------------------------------------------------------
__global__ void init_kernel() {
    int i = blockIdx.x * blockDim.x + threadIdx.x;
    if (i < N_NODES) g_deg[i] = 1.0f;
    float4* a4 = (float4*)g_agg32;
    if (i < N_NODES * 32 / 4) a4[i] = make_float4(0.f, 0.f, 0.f, 0.f);
}

__global__ void zero64_kernel() {
    int i = blockIdx.x * blockDim.x + threadIdx.x;
    float4* a4 = (float4*)g_agg64;
    if (i < N_NODES * 64 / 4) a4[i] = make_float4(0.f, 0.f, 0.f, 0.f);
}

// ---------------------------------------------------------------------------
// Degree: deg[dst] += 1 per edge
// ---------------------------------------------------------------------------
__global__ void deg_kernel(const void* ei) {
    int e = blockIdx.x * blockDim.x + threadIdx.x;
    if (e < N_EDGES) {
        int d = edge_idx(ei, N_EDGES + e);
        atomicAdd(&g_deg[d], 1.0f);
    }
}

__global__ void dinv_kernel() {
    int i = blockIdx.x * blockDim.x + threadIdx.x;
    if (i < N_NODES) g_dinv[i] = rsqrtf(fmaxf(g_deg[i], 1.0f));
}

// ys32 = dinv ⊙ x
__global__ void scale0_kernel(const float* __restrict__ x) {
    int i = blockIdx.x * blockDim.x + threadIdx.x;
    if (i < N_NODES * 32) g_ys32[i] = g_dinv[i >> 5] * x[i];
}

// ---------------------------------------------------------------------------
// Scatter: agg[dst] += ys[src]; float4 lanes, thread per (edge, chunk).
// Separate kernels per buffer so all scratch access is device-side.
// ---------------------------------------------------------------------------
__global__ void scatter32_kernel(const void* ei) {
    int i = blockIdx.x * blockDim.x + threadIdx.x;
    if (i >= N_EDGES * 8) return;
    int e = i >> 3;
    int c = i & 7;
    int s = edge_idx(ei, e);
    int d = edge_idx(ei, N_EDGES + e);
    const float4* ys4 = (const float4*)g_ys32;
    float4 v = ys4[s * 8 + c];
    red_add4(g_agg32 + (d * 8 + c) * 4, v);
}

__global__ void scatter64_kernel(const void* ei) {
    int i = blockIdx.x * blockDim.x + threadIdx.x;
    if (i >= N_EDGES * 16) return;
    int e = i >> 4;
    int c = i & 15;
    int s = edge_idx(ei, e);
    int d = edge_idx(ei, N_EDGES + e);
    const float4* ys4 = (const float4*)g_ys64;
    float4 v = ys4[s * 16 + c];
    red_add4(g_agg64 + (d * 16 + c) * 4, v);
}

// ---------------------------------------------------------------------------
// Combine layer 1: a = dinv*(agg32+ys32) [32] ; h1 = relu(a@W1+b1) [64]
//                  ys64 = dinv*h1.  Block: 256 threads = 4 nodes x 64.
// ---------------------------------------------------------------------------
__global__ void combine1_kernel(const float* __restrict__ W1,
                                const float* __restrict__ b1) {
    __shared__ float sW[32 * 64];
    __shared__ float sa[4][32];
    int tid = threadIdx.x;
    for (int i = tid; i < 32 * 64; i += 256) sW[i] = W1[i];

    int ln = tid >> 6;       // local node 0..3
    int j = tid & 63;        // output feature
    int node = blockIdx.x * 4 + ln;
    float dv = 0.f;
    if (node < N_NODES) {
        dv = g_dinv[node];
        if (j < 32)
            sa[ln][j] = dv * (g_agg32[node * 32 + j] + g_ys32[node * 32 + j]);
    }
    __syncthreads();
    if (node < N_NODES) {
        float sum = b1[j];
#pragma unroll
        for (int k = 0; k < 32; k++) sum = fmaf(sa[ln][k], sW[k * 64 + j], sum);
        float h = fmaxf(sum, 0.0f);
        g_ys64[node * 64 + j] = dv * h;
    }
}

// ---------------------------------------------------------------------------
// Combine layer 2 (in-place on ys64): a = dinv*(agg64+ys64) [64]
//   h2 = relu(a@W2+b2) [64] ; ys64 = dinv*h2.  256 threads = 4 nodes x 64.
// ---------------------------------------------------------------------------
__global__ void combine2_kernel(const float* __restrict__ W2,
                                const float* __restrict__ b2) {
    __shared__ float sW[64 * 64];
    __shared__ float sa[4][64];
    int tid = threadIdx.x;
    for (int i = tid; i < 64 * 64; i += 256) sW[i] = W2[i];

    int ln = tid >> 6;
    int j = tid & 63;
    int node = blockIdx.x * 4 + ln;
    float dv = 0.f;
    if (node < N_NODES) {
        dv = g_dinv[node];
        sa[ln][j] = dv * (g_agg64[node * 64 + j] + g_ys64[node * 64 + j]);
    }
    __syncthreads();
    if (node < N_NODES) {
        float sum = b2[j];
#pragma unroll
        for (int k = 0; k < 64; k++) sum = fmaf(sa[ln][k], sW[k * 64 + j], sum);
        float h = fmaxf(sum, 0.0f);
        g_ys64[node * 64 + j] = dv * h;   // per-(node,j) read happened pre-sync
    }
}

// ---------------------------------------------------------------------------
// Final: a = dinv*(agg64+ys64) [64] ; mu = a@W_mu+b_mu ; lv = a@W_lv+b_lv
//        z = mu + exp(0.5 lv)*eps.  Output layout: [z | mu | logvar].
//        256 threads = 8 nodes x 32.
// ---------------------------------------------------------------------------
__global__ void final_kernel(const float* __restrict__ W_mu,
                             const float* __restrict__ b_mu,
                             const float* __restrict__ W_lv,
                             const float* __restrict__ b_lv,
                             const float* __restrict__ eps,
                             float* __restrict__ out) {
    __shared__ float sWm[64 * 32];
    __shared__ float sWl[64 * 32];
    __shared__ float sa[8][64];
    int tid = threadIdx.x;
    for (int i = tid; i < 64 * 32; i += 256) { sWm[i] = W_mu[i]; sWl[i] = W_lv[i]; }

    int ln = tid >> 5;       // local node 0..7
    int j = tid & 31;        // output feature
    int node = blockIdx.x * 8 + ln;
    if (node < N_NODES) {
        float dv = g_dinv[node];
        sa[ln][j]      = dv * (g_agg64[node * 64 + j]      + g_ys64[node * 64 + j]);
        sa[ln][j + 32] = dv * (g_agg64[node * 64 + j + 32] + g_ys64[node * 64 + j + 32]);
    }
    __syncthreads();
    if (node < N_NODES) {
        float mu = b_mu[j];
        float lv = b_lv[j];
#pragma unroll
        for (int k = 0; k < 64; k++) {
            float a = sa[ln][k];
            mu = fmaf(a, sWm[k * 32 + j], mu);
            lv = fmaf(a, sWl[k * 32 + j], lv);
        }
        float z = fmaf(expf(0.5f * lv), eps[node * 32 + j], mu);
        int o = node * 32 + j;
        out[o] = z;
        out[NZ + o] = mu;
        out[2 * NZ + o] = lv;
    }
}

// ---------------------------------------------------------------------------
// Launch
// ---------------------------------------------------------------------------
extern "C" void kernel_launch(void* const* d_in, const int* in_sizes, int n_in,
                              void* d_out, int out_size) {
    const float* x    = (const float*)d_in[0];
    const void*  ei   = d_in[1];
    const float* W1   = (const float*)d_in[2];
    const float* b1   = (const float*)d_in[3];
    const float* W2   = (const float*)d_in[4];
    const float* b2   = (const float*)d_in[5];
    const float* W_mu = (const float*)d_in[6];
    const float* b_mu = (const float*)d_in[7];
    const float* W_lv = (const float*)d_in[8];
    const float* b_lv = (const float*)d_in[9];
    const float* eps  = (const float*)d_in[10];
    float* out = (float*)d_out;

    const int TB = 256;
    auto grid = [](long long n, int tb) { return (int)((n + tb - 1) / tb); };

    detect_kernel<<<1, 32>>>(ei);
    init_kernel<<<grid(N_NODES * 32 / 4, TB), TB>>>();           // deg=1 + zero agg32
    deg_kernel<<<grid(N_EDGES, TB), TB>>>(ei);
    dinv_kernel<<<grid(N_NODES, TB), TB>>>();
    scale0_kernel<<<grid((long long)N_NODES * 32, TB), TB>>>(x);

    // Layer 1: aggregate the 32-dim scaled input (P commutes with W)
    scatter32_kernel<<<grid((long long)N_EDGES * 8, TB), TB>>>(ei);
    combine1_kernel<<<(N_NODES + 3) / 4, 256>>>(W1, b1);

    // Layer 2: aggregate 64-dim
    zero64_kernel<<<grid(N_NODES * 64 / 4, TB), TB>>>();
    scatter64_kernel<<<grid((long long)N_EDGES * 16, TB), TB>>>(ei);
    combine2_kernel<<<(N_NODES + 3) / 4, 256>>>(W2, b2);

    // Heads: ONE shared 64-dim aggregation feeds both mu and logvar
    zero64_kernel<<<grid(N_NODES * 64 / 4, TB), TB>>>();
    scatter64_kernel<<<grid((long long)N_EDGES * 16, TB), TB>>>(ei);
    final_kernel<<<(N_NODES + 7) / 8, 256>>>(W_mu, b_mu, W_lv, b_lv, eps, out);
}

// round 3
// speedup vs baseline: 1.0203x; 1.0203x over previous
#include <cuda_runtime.h>
#include <cuda_bf16.h>

// Problem constants (fixed by the reference setup)
constexpr int N_NODES = 50000;
constexpr int N_EDGES = 800000;
constexpr int NZ = N_NODES * 32;

// Scratch (device globals; referenced ONLY from device code — host-side
// references to __device__ symbols pass the host shadow address on GB300/ATS).
__device__ __align__(16) float g_dinv[N_NODES];
__device__ __align__(16) float g_ys32[N_NODES * 32];   // dinv * x
__device__ __align__(16) float g_bufA[N_NODES * 64];   // dinv * h1
__device__ __align__(16) float g_bufB[N_NODES * 64];   // dinv * h2
__device__ int g_cnt[N_NODES];          // histogram, then fill-cursor
__device__ int g_row[N_NODES + 1];      // CSR row offsets (by dst)
__device__ int g_srcs[N_EDGES];         // src ids sorted by dst
__device__ int g_is64;

// ---------------------------------------------------------------------------
__device__ __forceinline__ int edge_idx(const void* p, int pos) {
    if (g_is64) return (int)((const long long*)p)[pos];
    return ((const int*)p)[pos];
}

// Detect int64 vs int32 edge_index (JAX may demote int64 -> int32).
__global__ void detect_kernel(const void* ei) {
    if (threadIdx.x == 0 && blockIdx.x == 0) {
        const long long* p = (const long long*)ei;
        int ok = 1;
        for (int i = 0; i < 256; i++) {
            long long v = p[i];
            if (v < 0 || v >= N_NODES) { ok = 0; break; }
        }
        g_is64 = ok;
    }
}

__global__ void zero_cnt_kernel() {
    int i = blockIdx.x * blockDim.x + threadIdx.x;
    if (i < N_NODES) g_cnt[i] = 0;
}

// Histogram of dst
__global__ void hist_kernel(const void* ei) {
    int e = blockIdx.x * blockDim.x + threadIdx.x;
    if (e < N_EDGES) atomicAdd(&g_cnt[edge_idx(ei, N_EDGES + e)], 1);
}

// Single-block scan: row offsets, dinv, cursor (reuses g_cnt as cursor).
__global__ void scan_kernel() {
    constexpr int T = 1024;
    constexpr int CH = (N_NODES + T - 1) / T;   // 49
    __shared__ int sh[T];
    int t = threadIdx.x;
    int lo = t * CH, hi = min(lo + CH, N_NODES);
    int s = 0;
    for (int i = lo; i < hi; i++) s += g_cnt[i];
    sh[t] = s;
    __syncthreads();
    for (int off = 1; off < T; off <<= 1) {
        int v = (t >= off) ? sh[t - off] : 0;
        __syncthreads();
        sh[t] += v;
        __syncthreads();
    }
    int run = sh[t] - s;   // exclusive prefix
    for (int i = lo; i < hi; i++) {
        int c = g_cnt[i];
        g_row[i] = run;
        g_cnt[i] = run;                     // cursor for fill pass
        g_dinv[i] = rsqrtf((float)(c + 1)); // deg incl. self-loop, >= 1
        run += c;
    }
    if (t == T - 1) g_row[N_NODES] = run;   // == N_EDGES
}

// Bucket fill: csr src list sorted by dst
__global__ void fill_kernel(const void* ei) {
    int e = blockIdx.x * blockDim.x + threadIdx.x;
    if (e < N_EDGES) {
        int s = edge_idx(ei, e);
        int d = edge_idx(ei, N_EDGES + e);
        int pos = atomicAdd(&g_cnt[d], 1);
        g_srcs[pos] = s;
    }
}

// ys32 = dinv ⊙ x  (float4 lanes)
__global__ void scale0_kernel(const float* __restrict__ x) {
    int i = blockIdx.x * blockDim.x + threadIdx.x;
    if (i < N_NODES * 8) {
        float4 v = ((const float4*)x)[i];
        float dv = g_dinv[i >> 3];
        ((float4*)g_ys32)[i] = make_float4(dv * v.x, dv * v.y, dv * v.z, dv * v.w);
    }
}

// ---------------------------------------------------------------------------
// Fused pull + GEMM kernels. Block = 256 threads = 8 warps; one warp per node;
// grid-stride loop over node groups so W is loaded into shared once per block.
// ---------------------------------------------------------------------------

// Layer 1: a[32] = dinv*(Σ ys32[src] + ys32[n]); bufA = dinv*relu(a@W1 + b1)
__global__ void __launch_bounds__(256) pull1_kernel(
    const float* __restrict__ W1, const float* __restrict__ b1) {
    __shared__ float sW[32 * 64];
    __shared__ float sb[64];
    __shared__ float4 sa[8][8];   // 8 warps x 32 floats
    int tid = threadIdx.x;
    for (int i = tid; i < 32 * 64; i += 256) sW[i] = W1[i];
    if (tid < 64) sb[tid] = b1[tid];
    __syncthreads();

    int w = tid >> 5, lane = tid & 31;
    for (int n = blockIdx.x * 8 + w; n < N_NODES; n += gridDim.x * 8) {
        float acc = g_ys32[n * 32 + lane];
        int e = g_row[n], end = g_row[n + 1];
        for (; e + 1 < end; e += 2) {
            int s0 = g_srcs[e], s1 = g_srcs[e + 1];
            acc += g_ys32[s0 * 32 + lane] + g_ys32[s1 * 32 + lane];
        }
        if (e < end) acc += g_ys32[g_srcs[e] * 32 + lane];
        float dv = g_dinv[n];
        ((float*)sa[w])[lane] = dv * acc;
        __syncwarp();
        // GEMM: this lane computes outputs 2*lane, 2*lane+1
        float s0 = sb[2 * lane], s1 = sb[2 * lane + 1];
#pragma unroll
        for (int k4 = 0; k4 < 8; k4++) {
            float4 a = sa[w][k4];
            float2 r0 = *(const float2*)&sW[(4 * k4 + 0) * 64 + 2 * lane];
            float2 r1 = *(const float2*)&sW[(4 * k4 + 1) * 64 + 2 * lane];
            float2 r2 = *(const float2*)&sW[(4 * k4 + 2) * 64 + 2 * lane];
            float2 r3 = *(const float2*)&sW[(4 * k4 + 3) * 64 + 2 * lane];
            s0 = fmaf(a.x, r0.x, s0); s1 = fmaf(a.x, r0.y, s1);
            s0 = fmaf(a.y, r1.x, s0); s1 = fmaf(a.y, r1.y, s1);
            s0 = fmaf(a.z, r2.x, s0); s1 = fmaf(a.z, r2.y, s1);
            s0 = fmaf(a.w, r3.x, s0); s1 = fmaf(a.w, r3.y, s1);
        }
        float2 o = make_float2(dv * fmaxf(s0, 0.f), dv * fmaxf(s1, 0.f));
        ((float2*)g_bufA)[n * 32 + lane] = o;
        __syncwarp();   // everyone done with sa[w] before next iteration
    }
}

// Layer 2: pull 64-dim from bufA, GEMM 64x64, bufB = dinv*relu(.)
__global__ void __launch_bounds__(256) pull2_kernel(
    const float* __restrict__ W2, const float* __restrict__ b2) {
    __shared__ float sW[64 * 64];
    __shared__ float sb[64];
    __shared__ float4 sa[8][16];  // 8 warps x 64 floats
    int tid = threadIdx.x;
    for (int i = tid; i < 64 * 64; i += 256) sW[i] = W2[i];
    if (tid < 64) sb[tid] = b2[tid];
    __syncthreads();

    int w = tid >> 5, lane = tid & 31;
    const float2* in2 = (const float2*)g_bufA;
    for (int n = blockIdx.x * 8 + w; n < N_NODES; n += gridDim.x * 8) {
        float2 acc = in2[n * 32 + lane];
        int e = g_row[n], end = g_row[n + 1];
        for (; e + 1 < end; e += 2) {
            int s0 = g_srcs[e], s1 = g_srcs[e + 1];
            float2 v0 = in2[s0 * 32 + lane];
            float2 v1 = in2[s1 * 32 + lane];
            acc.x += v0.x + v1.x;
            acc.y += v0.y + v1.y;
        }
        if (e < end) {
            float2 v = in2[g_srcs[e] * 32 + lane];
            acc.x += v.x; acc.y += v.y;
        }
        float dv = g_dinv[n];
        ((float2*)sa[w])[lane] = make_float2(dv * acc.x, dv * acc.y);
        __syncwarp();
        float s0 = sb[2 * lane], s1 = sb[2 * lane + 1];
#pragma unroll
        for (int k4 = 0; k4 < 16; k4++) {
            float4 a = sa[w][k4];
            float2 r0 = *(const float2*)&sW[(4 * k4 + 0) * 64 + 2 * lane];
            float2 r1 = *(const float2*)&sW[(4 * k4 + 1) * 64 + 2 * lane];
            float2 r2 = *(const float2*)&sW[(4 * k4 + 2) * 64 + 2 * lane];
            float2 r3 = *(const float2*)&sW[(4 * k4 + 3) * 64 + 2 * lane];
            s0 = fmaf(a.x, r0.x, s0); s1 = fmaf(a.x, r0.y, s1);
            s0 = fmaf(a.y, r1.x, s0); s1 = fmaf(a.y, r1.y, s1);
            s0 = fmaf(a.z, r2.x, s0); s1 = fmaf(a.z, r2.y, s1);
            s0 = fmaf(a.w, r3.x, s0); s1 = fmaf(a.w, r3.y, s1);
        }
        float2 o = make_float2(dv * fmaxf(s0, 0.f), dv * fmaxf(s1, 0.f));
        ((float2*)g_bufB)[n * 32 + lane] = o;
        __syncwarp();
    }
}

// Heads: pull 64-dim from bufB (ONE aggregation for both heads),
// mu = a@W_mu+b_mu, lv = a@W_lv+b_lv, z = mu + exp(0.5 lv)*eps.
// Output layout: [z | mu | logvar].
__global__ void __launch_bounds__(256) pull3_kernel(
    const float* __restrict__ W_mu, const float* __restrict__ b_mu,
    const float* __restrict__ W_lv, const float* __restrict__ b_lv,
    const float* __restrict__ eps, float* __restrict__ out) {
    __shared__ float2 sWml[64 * 32];   // interleaved {Wmu, Wlv}
    __shared__ float sbm[32], sbl[32];
    __shared__ float4 sa[8][16];
    int tid = threadIdx.x;
    for (int i = tid; i < 64 * 32; i += 256)
        sWml[i] = make_float2(W_mu[i], W_lv[i]);
    if (tid < 32) { sbm[tid] = b_mu[tid]; sbl[tid] = b_lv[tid]; }
    __syncthreads();

    int w = tid >> 5, lane = tid & 31;
    const float2* in2 = (const float2*)g_bufB;
    for (int n = blockIdx.x * 8 + w; n < N_NODES; n += gridDim.x * 8) {
        float2 acc = in2[n * 32 + lane];
        int e = g_row[n], end = g_row[n + 1];
        for (; e + 1 < end; e += 2) {
            int s0 = g_srcs[e], s1 = g_srcs[e + 1];
            float2 v0 = in2[s0 * 32 + lane];
            float2 v1 = in2[s1 * 32 + lane];
            acc.x += v0.x + v1.x;
            acc.y += v0.y + v1.y;
        }
        if (e < end) {
            float2 v = in2[g_srcs[e] * 32 + lane];
            acc.x += v.x; acc.y += v.y;
        }
        float dv = g_dinv[n];
        ((float2*)sa[w])[lane] = make_float2(dv * acc.x, dv * acc.y);
        __syncwarp();
        float mu = sbm[lane], lv = sbl[lane];
#pragma unroll
        for (int k4 = 0; k4 < 16; k4++) {
            float4 a = sa[w][k4];
            float2 m0 = sWml[(4 * k4 + 0) * 32 + lane];
            float2 m1 = sWml[(4 * k4 + 1) * 32 + lane];
            float2 m2 = sWml[(4 * k4 + 2) * 32 + lane];
            float2 m3 = sWml[(4 * k4 + 3) * 32 + lane];
            mu = fmaf(a.x, m0.x, mu); lv = fmaf(a.x, m0.y, lv);
            mu = fmaf(a.y, m1.x, mu); lv = fmaf(a.y, m1.y, lv);
            mu = fmaf(a.z, m2.x, mu); lv = fmaf(a.z, m2.y, lv);
            mu = fmaf(a.w, m3.x, mu); lv = fmaf(a.w, m3.y, lv);
        }
        float z = fmaf(expf(0.5f * lv), eps[n * 32 + lane], mu);
        int o = n * 32 + lane;
        out[o] = z;
        out[NZ + o] = mu;
        out[2 * NZ + o] = lv;
        __syncwarp();
    }
}

// ---------------------------------------------------------------------------
extern "C" void kernel_launch(void* const* d_in, const int* in_sizes, int n_in,
                              void* d_out, int out_size) {
    const float* x    = (const float*)d_in[0];
    const void*  ei   = d_in[1];
    const float* W1   = (const float*)d_in[2];
    const float* b1   = (const float*)d_in[3];
    const float* W2   = (const float*)d_in[4];
    const float* b2   = (const float*)d_in[5];
    const float* W_mu = (const float*)d_in[6];
    const float* b_mu = (const float*)d_in[7];
    const float* W_lv = (const float*)d_in[8];
    const float* b_lv = (const float*)d_in[9];
    const float* eps  = (const float*)d_in[10];
    float* out = (float*)d_out;

    const int TB = 256;
    auto grid = [](long long n, int tb) { return (int)((n + tb - 1) / tb); };
    const int PG = 1184;   // 8 blocks/SM worth of persistent pull blocks

    detect_kernel<<<1, 32>>>(ei);
    zero_cnt_kernel<<<grid(N_NODES, TB), TB>>>();
    hist_kernel<<<grid(N_EDGES, TB), TB>>>(ei);
    scan_kernel<<<1, 1024>>>();
    fill_kernel<<<grid(N_EDGES, TB), TB>>>(ei);
    scale0_kernel<<<grid(N_NODES * 8, TB), TB>>>(x);

    pull1_kernel<<<PG, 256>>>(W1, b1);
    pull2_kernel<<<PG, 256>>>(W2, b2);
    pull3_kernel<<<PG, 256>>>(W_mu, b_mu, W_lv, b_lv, eps, out);
}

// round 4
// speedup vs baseline: 1.6189x; 1.5867x over previous
#include <cuda_runtime.h>
#include <cuda_bf16.h>

// Problem constants (fixed by the reference setup)
constexpr int N_NODES = 50000;
constexpr int N_EDGES = 800000;
constexpr int NZ = N_NODES * 32;
constexpr int SCAN_B = 256;
constexpr int NB = (N_NODES + SCAN_B - 1) / SCAN_B;   // 196 scan blocks

// Scratch (device globals; referenced ONLY from device code — host-side
// references to __device__ symbols pass the host shadow address on GB300/ATS).
__device__ __align__(16) float g_dinv[N_NODES];
__device__ __align__(16) float g_ys32[N_NODES * 32];   // dinv * x
__device__ __align__(16) float g_bufA[N_NODES * 64];   // dinv * h1
__device__ __align__(16) float g_bufB[N_NODES * 64];   // dinv * h2
__device__ int g_cnt[N_NODES];          // histogram, then fill-cursor
__device__ int g_row[N_NODES + 1];      // CSR row offsets (by dst)
__device__ int g_srcs[N_EDGES];         // src ids sorted by dst
__device__ int g_bsum[NB];              // per-block count sums
__device__ int g_bpre[NB];              // exclusive prefix of block sums
__device__ int g_is64;

// ---------------------------------------------------------------------------
__device__ __forceinline__ int edge_idx(const void* p, int pos) {
    if (g_is64) return (int)((const long long*)p)[pos];
    return ((const int*)p)[pos];
}

// Detect int64 vs int32 edge_index + zero the histogram (fused).
__global__ void detect_zero_kernel(const void* ei) {
    int i = blockIdx.x * blockDim.x + threadIdx.x;
    if (i < N_NODES) g_cnt[i] = 0;
    if (i == 0) {
        const long long* p = (const long long*)ei;
        int ok = 1;
        for (int k = 0; k < 256; k++) {
            long long v = p[k];
            if (v < 0 || v >= N_NODES) { ok = 0; break; }
        }
        g_is64 = ok;
    }
}

// Histogram of dst
__global__ void hist_kernel(const void* ei) {
    int e = blockIdx.x * blockDim.x + threadIdx.x;
    if (e < N_EDGES) atomicAdd(&g_cnt[edge_idx(ei, N_EDGES + e)], 1);
}

// --- Two-level parallel exclusive scan of g_cnt -> g_row -----------------

// 1) per-block sums
__global__ void partial_kernel() {
    __shared__ int sh[SCAN_B];
    int i = blockIdx.x * SCAN_B + threadIdx.x;
    int v = (i < N_NODES) ? g_cnt[i] : 0;
    sh[threadIdx.x] = v;
    __syncthreads();
#pragma unroll
    for (int off = SCAN_B / 2; off > 0; off >>= 1) {
        if (threadIdx.x < off) sh[threadIdx.x] += sh[threadIdx.x + off];
        __syncthreads();
    }
    if (threadIdx.x == 0) g_bsum[blockIdx.x] = sh[0];
}

// 2) scan the NB block sums (single block)
__global__ void scan_bsum_kernel() {
    __shared__ int sh[SCAN_B];
    int t = threadIdx.x;
    int v = (t < NB) ? g_bsum[t] : 0;
    sh[t] = v;
    __syncthreads();
#pragma unroll
    for (int off = 1; off < SCAN_B; off <<= 1) {
        int u = (t >= off) ? sh[t - off] : 0;
        __syncthreads();
        sh[t] += u;
        __syncthreads();
    }
    if (t < NB) g_bpre[t] = sh[t] - v;   // exclusive
}

// 3) intra-block exclusive scan + block base -> row offsets, cursor, dinv
__global__ void offsets_kernel() {
    __shared__ int sh[SCAN_B];
    int t = threadIdx.x;
    int i = blockIdx.x * SCAN_B + t;
    int c = (i < N_NODES) ? g_cnt[i] : 0;
    sh[t] = c;
    __syncthreads();
#pragma unroll
    for (int off = 1; off < SCAN_B; off <<= 1) {
        int u = (t >= off) ? sh[t - off] : 0;
        __syncthreads();
        sh[t] += u;
        __syncthreads();
    }
    if (i < N_NODES) {
        int r = g_bpre[blockIdx.x] + sh[t] - c;   // exclusive global prefix
        g_row[i] = r;
        g_cnt[i] = r;                              // fill cursor
        g_dinv[i] = rsqrtf((float)(c + 1));        // deg incl. self-loop
    }
    if (i == 0) g_row[N_NODES] = N_EDGES;
}

// Bucket fill: csr src list sorted by dst
__global__ void fill_kernel(const void* ei) {
    int e = blockIdx.x * blockDim.x + threadIdx.x;
    if (e < N_EDGES) {
        int s = edge_idx(ei, e);
        int d = edge_idx(ei, N_EDGES + e);
        int pos = atomicAdd(&g_cnt[d], 1);
        g_srcs[pos] = s;
    }
}

// ys32 = dinv ⊙ x  (float4 lanes)
__global__ void scale0_kernel(const float* __restrict__ x) {
    int i = blockIdx.x * blockDim.x + threadIdx.x;
    if (i < N_NODES * 8) {
        float4 v = ((const float4*)x)[i];
        float dv = g_dinv[i >> 3];
        ((float4*)g_ys32)[i] = make_float4(dv * v.x, dv * v.y, dv * v.z, dv * v.w);
    }
}

// ---------------------------------------------------------------------------
// Fused pull + GEMM kernels. Block = 256 threads = 8 warps; one warp per node;
// grid-stride loop over node groups so W is loaded into shared once per block.
// ---------------------------------------------------------------------------

// Layer 1: a[32] = dinv*(Σ ys32[src] + ys32[n]); bufA = dinv*relu(a@W1 + b1)
__global__ void __launch_bounds__(256) pull1_kernel(
    const float* __restrict__ W1, const float* __restrict__ b1) {
    __shared__ float sW[32 * 64];
    __shared__ float sb[64];
    __shared__ float4 sa[8][8];   // 8 warps x 32 floats
    int tid = threadIdx.x;
    for (int i = tid; i < 32 * 64; i += 256) sW[i] = W1[i];
    if (tid < 64) sb[tid] = b1[tid];
    __syncthreads();

    int w = tid >> 5, lane = tid & 31;
    for (int n = blockIdx.x * 8 + w; n < N_NODES; n += gridDim.x * 8) {
        float acc = g_ys32[n * 32 + lane];
        int e = g_row[n], end = g_row[n + 1];
        for (; e + 1 < end; e += 2) {
            int s0 = g_srcs[e], s1 = g_srcs[e + 1];
            acc += g_ys32[s0 * 32 + lane] + g_ys32[s1 * 32 + lane];
        }
        if (e < end) acc += g_ys32[g_srcs[e] * 32 + lane];
        float dv = g_dinv[n];
        ((float*)sa[w])[lane] = dv * acc;
        __syncwarp();
        // GEMM: this lane computes outputs 2*lane, 2*lane+1
        float s0 = sb[2 * lane], s1 = sb[2 * lane + 1];
#pragma unroll
        for (int k4 = 0; k4 < 8; k4++) {
            float4 a = sa[w][k4];
            float2 r0 = *(const float2*)&sW[(4 * k4 + 0) * 64 + 2 * lane];
            float2 r1 = *(const float2*)&sW[(4 * k4 + 1) * 64 + 2 * lane];
            float2 r2 = *(const float2*)&sW[(4 * k4 + 2) * 64 + 2 * lane];
            float2 r3 = *(const float2*)&sW[(4 * k4 + 3) * 64 + 2 * lane];
            s0 = fmaf(a.x, r0.x, s0); s1 = fmaf(a.x, r0.y, s1);
            s0 = fmaf(a.y, r1.x, s0); s1 = fmaf(a.y, r1.y, s1);
            s0 = fmaf(a.z, r2.x, s0); s1 = fmaf(a.z, r2.y, s1);
            s0 = fmaf(a.w, r3.x, s0); s1 = fmaf(a.w, r3.y, s1);
        }
        float2 o = make_float2(dv * fmaxf(s0, 0.f), dv * fmaxf(s1, 0.f));
        ((float2*)g_bufA)[n * 32 + lane] = o;
        __syncwarp();   // everyone done with sa[w] before next iteration
    }
}

// Layer 2: pull 64-dim from bufA, GEMM 64x64, bufB = dinv*relu(.)
__global__ void __launch_bounds__(256) pull2_kernel(
    const float* __restrict__ W2, const float* __restrict__ b2) {
    __shared__ float sW[64 * 64];
    __shared__ float sb[64];
    __shared__ float4 sa[8][16];  // 8 warps x 64 floats
    int tid = threadIdx.x;
    for (int i = tid; i < 64 * 64; i += 256) sW[i] = W2[i];
    if (tid < 64) sb[tid] = b2[tid];
    __syncthreads();

    int w = tid >> 5, lane = tid & 31;
    const float2* in2 = (const float2*)g_bufA;
    for (int n = blockIdx.x * 8 + w; n < N_NODES; n += gridDim.x * 8) {
        float2 acc = in2[n * 32 + lane];
        int e = g_row[n], end = g_row[n + 1];
        for (; e + 1 < end; e += 2) {
            int s0 = g_srcs[e], s1 = g_srcs[e + 1];
            float2 v0 = in2[s0 * 32 + lane];
            float2 v1 = in2[s1 * 32 + lane];
            acc.x += v0.x + v1.x;
            acc.y += v0.y + v1.y;
        }
        if (e < end) {
            float2 v = in2[g_srcs[e] * 32 + lane];
            acc.x += v.x; acc.y += v.y;
        }
        float dv = g_dinv[n];
        ((float2*)sa[w])[lane] = make_float2(dv * acc.x, dv * acc.y);
        __syncwarp();
        float s0 = sb[2 * lane], s1 = sb[2 * lane + 1];
#pragma unroll
        for (int k4 = 0; k4 < 16; k4++) {
            float4 a = sa[w][k4];
            float2 r0 = *(const float2*)&sW[(4 * k4 + 0) * 64 + 2 * lane];
            float2 r1 = *(const float2*)&sW[(4 * k4 + 1) * 64 + 2 * lane];
            float2 r2 = *(const float2*)&sW[(4 * k4 + 2) * 64 + 2 * lane];
            float2 r3 = *(const float2*)&sW[(4 * k4 + 3) * 64 + 2 * lane];
            s0 = fmaf(a.x, r0.x, s0); s1 = fmaf(a.x, r0.y, s1);
            s0 = fmaf(a.y, r1.x, s0); s1 = fmaf(a.y, r1.y, s1);
            s0 = fmaf(a.z, r2.x, s0); s1 = fmaf(a.z, r2.y, s1);
            s0 = fmaf(a.w, r3.x, s0); s1 = fmaf(a.w, r3.y, s1);
        }
        float2 o = make_float2(dv * fmaxf(s0, 0.f), dv * fmaxf(s1, 0.f));
        ((float2*)g_bufB)[n * 32 + lane] = o;
        __syncwarp();
    }
}

// Heads: pull 64-dim from bufB (ONE aggregation for both heads),
// mu = a@W_mu+b_mu, lv = a@W_lv+b_lv, z = mu + exp(0.5 lv)*eps.
// Output layout: [z | mu | logvar].
__global__ void __launch_bounds__(256) pull3_kernel(
    const float* __restrict__ W_mu, const float* __restrict__ b_mu,
    const float* __restrict__ W_lv, const float* __restrict__ b_lv,
    const float* __restrict__ eps, float* __restrict__ out) {
    __shared__ float2 sWml[64 * 32];   // interleaved {Wmu, Wlv}
    __shared__ float sbm[32], sbl[32];
    __shared__ float4 sa[8][16];
    int tid = threadIdx.x;
    for (int i = tid; i < 64 * 32; i += 256)
        sWml[i] = make_float2(W_mu[i], W_lv[i]);
    if (tid < 32) { sbm[tid] = b_mu[tid]; sbl[tid] = b_lv[tid]; }
    __syncthreads();

    int w = tid >> 5, lane = tid & 31;
    const float2* in2 = (const float2*)g_bufB;
    for (int n = blockIdx.x * 8 + w; n < N_NODES; n += gridDim.x * 8) {
        float2 acc = in2[n * 32 + lane];
        int e = g_row[n], end = g_row[n + 1];
        for (; e + 1 < end; e += 2) {
            int s0 = g_srcs[e], s1 = g_srcs[e + 1];
            float2 v0 = in2[s0 * 32 + lane];
            float2 v1 = in2[s1 * 32 + lane];
            acc.x += v0.x + v1.x;
            acc.y += v0.y + v1.y;
        }
        if (e < end) {
            float2 v = in2[g_srcs[e] * 32 + lane];
            acc.x += v.x; acc.y += v.y;
        }
        float dv = g_dinv[n];
        ((float2*)sa[w])[lane] = make_float2(dv * acc.x, dv * acc.y);
        __syncwarp();
        float mu = sbm[lane], lv = sbl[lane];
#pragma unroll
        for (int k4 = 0; k4 < 16; k4++) {
            float4 a = sa[w][k4];
            float2 m0 = sWml[(4 * k4 + 0) * 32 + lane];
            float2 m1 = sWml[(4 * k4 + 1) * 32 + lane];
            float2 m2 = sWml[(4 * k4 + 2) * 32 + lane];
            float2 m3 = sWml[(4 * k4 + 3) * 32 + lane];
            mu = fmaf(a.x, m0.x, mu); lv = fmaf(a.x, m0.y, lv);
            mu = fmaf(a.y, m1.x, mu); lv = fmaf(a.y, m1.y, lv);
            mu = fmaf(a.z, m2.x, mu); lv = fmaf(a.z, m2.y, lv);
            mu = fmaf(a.w, m3.x, mu); lv = fmaf(a.w, m3.y, lv);
        }
        float z = fmaf(expf(0.5f * lv), eps[n * 32 + lane], mu);
        int o = n * 32 + lane;
        out[o] = z;
        out[NZ + o] = mu;
        out[2 * NZ + o] = lv;
        __syncwarp();
    }
}

// ---------------------------------------------------------------------------
extern "C" void kernel_launch(void* const* d_in, const int* in_sizes, int n_in,
                              void* d_out, int out_size) {
    const float* x    = (const float*)d_in[0];
    const void*  ei   = d_in[1];
    const float* W1   = (const float*)d_in[2];
    const float* b1   = (const float*)d_in[3];
    const float* W2   = (const float*)d_in[4];
    const float* b2   = (const float*)d_in[5];
    const float* W_mu = (const float*)d_in[6];
    const float* b_mu = (const float*)d_in[7];
    const float* W_lv = (const float*)d_in[8];
    const float* b_lv = (const float*)d_in[9];
    const float* eps  = (const float*)d_in[10];
    float* out = (float*)d_out;

    const int TB = 256;
    auto grid = [](long long n, int tb) { return (int)((n + tb - 1) / tb); };
    const int PG = 1184;   // persistent pull blocks (8/SM x 148)

    detect_zero_kernel<<<grid(N_NODES, TB), TB>>>(ei);
    hist_kernel<<<grid(N_EDGES, TB), TB>>>(ei);
    partial_kernel<<<NB, SCAN_B>>>();
    scan_bsum_kernel<<<1, SCAN_B>>>();
    offsets_kernel<<<NB, SCAN_B>>>();
    fill_kernel<<<grid(N_EDGES, TB), TB>>>(ei);
    scale0_kernel<<<grid(N_NODES * 8, TB), TB>>>(x);

    pull1_kernel<<<PG, 256>>>(W1, b1);
    pull2_kernel<<<PG, 256>>>(W2, b2);
    pull3_kernel<<<PG, 256>>>(W_mu, b_mu, W_lv, b_lv, eps, out);
}